// round 1
// baseline (speedup 1.0000x reference)
#include <cuda_runtime.h>
#include <cuda_bf16.h>

#define NBIN 25
#define WARPS_PER_BLOCK 8
#define MAX_B 64

// Scratch accumulators (no dynamic allocation allowed).
__device__ float g_num[MAX_B * NBIN];   // sum_n sa[n,k] * label[n]   per (b,k)
__device__ float g_den[MAX_B * NBIN];   // sum_n sa[n,k]              per (b,k)
__device__ float g_lab[MAX_B];          // sum_n label[n]             per b

// ---------------------------------------------------------------------------
// Zero the scratch (required every replay: graph re-executes from scratch).
// ---------------------------------------------------------------------------
__global__ void qap_zero(int B) {
    int i = blockIdx.x * blockDim.x + threadIdx.x;
    if (i < B * NBIN) { g_num[i] = 0.0f; g_den[i] = 0.0f; }
    if (i < B)        { g_lab[i] = 0.0f; }
}

// ---------------------------------------------------------------------------
// Main streaming kernel: warp-per-row cosine sim + triangular soft binning.
//   qX  : (B, 128) f32  viewed as float4 (B, 32)
//   dXs : (B, N, 128) f32 viewed as float4 (B, N, 32)
// Grid: (chunks, B), block: 256 threads (8 warps).
// ---------------------------------------------------------------------------
__global__ __launch_bounds__(WARPS_PER_BLOCK * 32)
void qap_main(const float4* __restrict__ qX4,
              const float4* __restrict__ dXs4,
              const int*    __restrict__ labels,
              int B, int N) {
    const int b    = blockIdx.y;
    const int lane = threadIdx.x & 31;
    const int warp = threadIdx.x >> 5;
    const int gw     = blockIdx.x * WARPS_PER_BLOCK + warp;   // warp id within b
    const int nWarps = gridDim.x * WARPS_PER_BLOCK;

    // Per-lane slice of qX[b] (one float4 per lane covers M=128 exactly).
    const float4 q = qX4[(size_t)b * 32 + lane];

    // 1/||q|| with eps clamp (computed redundantly per warp; negligible).
    float qs = q.x * q.x + q.y * q.y + q.z * q.z + q.w * q.w;
    #pragma unroll
    for (int off = 16; off; off >>= 1) qs += __shfl_xor_sync(0xFFFFFFFFu, qs, off);
    const float qn = fmaxf(sqrtf(qs), 1e-8f);

    const float4* __restrict__ drow = dXs4   + (size_t)b * N * 32;
    const int*    __restrict__ lrow = labels + (size_t)b * N;

    // Lane k accumulates bin k (k < NBIN). Center c_k = 1 - k*DELTA, DELTA = 1/12.
    const float ck   = 1.0f - (float)lane * (2.0f / (float)(NBIN - 1));
    const float invD = (float)(NBIN - 1) * 0.5f;   // 12 = 1/DELTA

    float accNum = 0.0f, accDen = 0.0f, accLab = 0.0f;

    const int nGroups = (N + 31) >> 5;
    for (int g = gw; g < nGroups; g += nWarps) {
        const int base = g << 5;
        const int cnt  = min(32, N - base);
        // Coalesced label load for the 32-row group.
        const int lab32 = (lane < cnt) ? lrow[base + lane] : 0;

        #pragma unroll 4
        for (int i = 0; i < cnt; i++) {
            const float4 x = drow[(size_t)(base + i) * 32 + lane];

            float d = q.x * x.x + q.y * x.y + q.z * x.z + q.w * x.w;  // dot partial
            float s = x.x * x.x + x.y * x.y + x.z * x.z + x.w * x.w;  // sumsq partial
            #pragma unroll
            for (int off = 16; off; off >>= 1) {
                d += __shfl_xor_sync(0xFFFFFFFFu, d, off);
                s += __shfl_xor_sync(0xFFFFFFFFu, s, off);
            }

            const float dn  = fmaxf(sqrtf(s), 1e-8f);
            const float sim = d / (qn * dn);
            const float lab = (float)__shfl_sync(0xFFFFFFFFu, lab32, i);

            // Exact reference soft-assignment for this lane's bin.
            const float sa = fmaxf(0.0f, 1.0f - fabsf(sim - ck) * invD);
            accDen += sa;
            accNum += sa * lab;
            accLab += lab;   // identical across lanes; only lane 0's is used
        }
    }

    if (lane < NBIN) {
        atomicAdd(&g_den[b * NBIN + lane], accDen);
        atomicAdd(&g_num[b * NBIN + lane], accNum);
    }
    if (lane == 0) atomicAdd(&g_lab[b], accLab);
}

// ---------------------------------------------------------------------------
// Finalize: per-b cumsums -> precision/recall -> AP, then mean over B.
// One warp; thread b handles batch b (B <= 32).
// ---------------------------------------------------------------------------
__global__ void qap_final(float* __restrict__ out, int B) {
    const int b = threadIdx.x;
    float ap = 0.0f;
    if (b < B) {
        float pd = 0.0f;           // cumsum of num_per_bin  ("pDen" in reference)
        float pn = 1e-16f;         // EPS_P + cumsum of den_per_bin ("pNum")
        const float invLab = 1.0f / g_lab[b];
        #pragma unroll
        for (int k = 0; k < NBIN; k++) {
            const float nm = g_num[b * NBIN + k];
            const float dn = g_den[b * NBIN + k];
            pd += nm;
            pn += dn;
            ap += (pd / pn) * (nm * invLab);
        }
    }
    #pragma unroll
    for (int off = 16; off; off >>= 1) ap += __shfl_xor_sync(0xFFFFFFFFu, ap, off);
    if (threadIdx.x == 0) out[0] = ap / (float)B;
}

// ---------------------------------------------------------------------------
extern "C" void kernel_launch(void* const* d_in, const int* in_sizes, int n_in,
                              void* d_out, int out_size) {
    const float4* qX4    = (const float4*)d_in[0];
    const float4* dXs4   = (const float4*)d_in[1];
    const int*    labels = (const int*)d_in[2];
    float* out = (float*)d_out;

    const int M = 128;
    const int B = in_sizes[0] / M;               // 16
    const int N = in_sizes[1] / in_sizes[0];     // 50000

    qap_zero<<<1, 512>>>(B);

    dim3 grid(64, B);                            // 1024 blocks, ~7/SM
    qap_main<<<grid, WARPS_PER_BLOCK * 32>>>(qX4, dXs4, labels, B, N);

    qap_final<<<1, 32>>>(out, B);
}

// round 2
// speedup vs baseline: 1.8244x; 1.8244x over previous
#include <cuda_runtime.h>
#include <cuda_bf16.h>

#define NBIN 25
#define WARPS_PER_BLOCK 8
#define MAX_B 64

// Scratch accumulators (no dynamic allocation allowed).
__device__ float g_num[MAX_B * NBIN];   // sum_n sa[n,k] * label[n]   per (b,k)
__device__ float g_den[MAX_B * NBIN];   // sum_n sa[n,k]              per (b,k)
__device__ float g_lab[MAX_B];          // sum_n label[n]             per b

// ---------------------------------------------------------------------------
__global__ void qap_zero(int B) {
    int i = blockIdx.x * blockDim.x + threadIdx.x;
    if (i < B * NBIN) { g_num[i] = 0.0f; g_den[i] = 0.0f; }
    if (i < B)        { g_lab[i] = 0.0f; }
}

// ---------------------------------------------------------------------------
// Main streaming kernel.
// Layout: 8 lanes per row, 4 rows per warp.
//   lane = 8*grp + sub ; grp in [0,4) selects the row, sub in [0,8) the slice.
//   Lane loads float4 indices sub, sub+8, sub+16, sub+24 of its row
//   -> each LDG.128 instruction covers 4 contiguous 128B lines (full coalesce).
// Reduction: 3 butterfly levels (masks 1,2,4) for dot and sumsq.
// Binning: lane k (<25) owns bin k; sims broadcast per row via 1 shfl each.
// ---------------------------------------------------------------------------
__global__ __launch_bounds__(WARPS_PER_BLOCK * 32)
void qap_main(const float4* __restrict__ qX4,
              const float4* __restrict__ dXs4,
              const int*    __restrict__ labels,
              int B, int N) {
    const int b    = blockIdx.y;
    const int lane = threadIdx.x & 31;
    const int warp = threadIdx.x >> 5;
    const int sub  = lane & 7;    // slice within row
    const int grp  = lane >> 3;   // row within warp-iteration
    const int gw     = blockIdx.x * WARPS_PER_BLOCK + warp;
    const int nWarps = gridDim.x * WARPS_PER_BLOCK;

    // Per-lane slices of qX[b]: float4 indices sub + 8j.
    float4 qv[4];
    #pragma unroll
    for (int j = 0; j < 4; j++) qv[j] = qX4[(size_t)b * 32 + sub + 8 * j];

    // ||q||: each 8-lane group covers all 32 float4s. Reduce within group.
    float qs = 0.0f;
    #pragma unroll
    for (int j = 0; j < 4; j++)
        qs += qv[j].x * qv[j].x + qv[j].y * qv[j].y + qv[j].z * qv[j].z + qv[j].w * qv[j].w;
    #pragma unroll
    for (int off = 4; off; off >>= 1) qs += __shfl_xor_sync(0xFFFFFFFFu, qs, off);
    const float invqn = 1.0f / fmaxf(sqrtf(qs), 1e-8f);

    const float4* __restrict__ drow = dXs4   + (size_t)b * N * 32;
    const int*    __restrict__ lrow = labels + (size_t)b * N;

    // Lane k accumulates bin k. DELTA = 2/(NBIN-1) = 1/12.
    const float ck   = 1.0f - (float)lane * (2.0f / (float)(NBIN - 1));
    const float invD = (float)(NBIN - 1) * 0.5f;   // 12

    float accNum = 0.0f, accDen = 0.0f, accLab = 0.0f;

    const int nTiles = (N + 31) >> 5;      // 32-row tiles
    for (int t = gw; t < nTiles; t += nWarps) {
        const int tile = t << 5;
        const int cnt  = min(32, N - tile);
        const int lab32 = (lane < cnt) ? lrow[tile + lane] : 0;
        accLab += (float)lab32;            // per-lane; reduced once at the end

        #pragma unroll 2
        for (int i = 0; i < 8; i++) {      // 4 rows per iteration
            const int r0 = tile + (i << 2);
            if (r0 >= N) break;
            const int myrow   = r0 + grp;
            const int loadrow = (myrow < N) ? myrow : (N - 1);
            const float4* __restrict__ p = drow + (size_t)loadrow * 32 + sub;

            float d = 0.0f, s = 0.0f;
            #pragma unroll
            for (int j = 0; j < 4; j++) {
                const float4 x = __ldcs(&p[8 * j]);
                d += qv[j].x * x.x + qv[j].y * x.y + qv[j].z * x.z + qv[j].w * x.w;
                s += x.x * x.x + x.y * x.y + x.z * x.z + x.w * x.w;
            }
            #pragma unroll
            for (int off = 4; off; off >>= 1) {
                d += __shfl_xor_sync(0xFFFFFFFFu, d, off);
                s += __shfl_xor_sync(0xFFFFFFFFu, s, off);
            }
            const float dn  = fmaxf(sqrtf(s), 1e-8f);
            const float sim = __fdividef(d * invqn, dn);

            // Binning: broadcast each row's sim + label; lane<25 owns its bin.
            #pragma unroll
            for (int r = 0; r < 4; r++) {
                if (r0 + r >= N) break;   // uniform branch
                const float simr = __shfl_sync(0xFFFFFFFFu, sim, r << 3);
                const float labr = (float)__shfl_sync(0xFFFFFFFFu, lab32, (i << 2) + r);
                const float sa = fmaxf(0.0f, 1.0f - fabsf(simr - ck) * invD);
                accDen += sa;
                accNum += sa * labr;
            }
        }
    }

    // Label total: reduce per-lane partials across the warp.
    #pragma unroll
    for (int off = 16; off; off >>= 1)
        accLab += __shfl_xor_sync(0xFFFFFFFFu, accLab, off);

    if (lane < NBIN) {
        atomicAdd(&g_den[b * NBIN + lane], accDen);
        atomicAdd(&g_num[b * NBIN + lane], accNum);
    }
    if (lane == 0) atomicAdd(&g_lab[b], accLab);
}

// ---------------------------------------------------------------------------
__global__ void qap_final(float* __restrict__ out, int B) {
    const int b = threadIdx.x;
    float ap = 0.0f;
    if (b < B) {
        float pd = 0.0f;           // cumsum num_per_bin  ("pDen")
        float pn = 1e-16f;         // EPS_P + cumsum den_per_bin ("pNum")
        const float invLab = 1.0f / g_lab[b];
        #pragma unroll
        for (int k = 0; k < NBIN; k++) {
            const float nm = g_num[b * NBIN + k];
            const float dn = g_den[b * NBIN + k];
            pd += nm;
            pn += dn;
            ap += (pd / pn) * (nm * invLab);
        }
    }
    #pragma unroll
    for (int off = 16; off; off >>= 1) ap += __shfl_xor_sync(0xFFFFFFFFu, ap, off);
    if (threadIdx.x == 0) out[0] = ap / (float)B;
}

// ---------------------------------------------------------------------------
extern "C" void kernel_launch(void* const* d_in, const int* in_sizes, int n_in,
                              void* d_out, int out_size) {
    const float4* qX4    = (const float4*)d_in[0];
    const float4* dXs4   = (const float4*)d_in[1];
    const int*    labels = (const int*)d_in[2];
    float* out = (float*)d_out;

    const int M = 128;
    const int B = in_sizes[0] / M;               // 16
    const int N = in_sizes[1] / in_sizes[0];     // 50000

    qap_zero<<<1, 512>>>(B);

    dim3 grid(64, B);
    qap_main<<<grid, WARPS_PER_BLOCK * 32>>>(qX4, dXs4, labels, B, N);

    qap_final<<<1, 32>>>(out, B);
}

// round 3
// speedup vs baseline: 2.0430x; 1.1199x over previous
#include <cuda_runtime.h>
#include <cuda_bf16.h>

#define NBIN 25
#define WARPS_PER_BLOCK 8
#define MAX_B 64
#define MAX_SLOTS 1024

// Per-block partial sums, written with plain stores every launch (no zeroing
// needed -> no zero kernel in the graph). Layout: slot = s*B + b so the
// final-reduction reads are fully coalesced (stride B*NBIN across threads).
__device__ float g_pnum[MAX_SLOTS * NBIN];
__device__ float g_pden[MAX_SLOTS * NBIN];
__device__ float g_plab[MAX_SLOTS];

// ---------------------------------------------------------------------------
// Main streaming kernel. 8 lanes per row, 4 rows per warp.
// grid = B * S blocks (S slices per batch), exactly one wave at 4 blocks/SM.
// ---------------------------------------------------------------------------
__global__ __launch_bounds__(WARPS_PER_BLOCK * 32, 4)
void qap_main(const float4* __restrict__ qX4,
              const float4* __restrict__ dXs4,
              const int*    __restrict__ labels,
              int B, int N, int S) {
    const int b    = blockIdx.x / S;     // batch
    const int s    = blockIdx.x - b * S; // slice within batch
    const int lane = threadIdx.x & 31;
    const int warp = threadIdx.x >> 5;
    const int sub  = lane & 7;           // slice within row (8 lanes/row)
    const int grp  = lane >> 3;          // row within warp-iteration (4 rows)
    const int gw     = s * WARPS_PER_BLOCK + warp;
    const int nWarps = S * WARPS_PER_BLOCK;

    // Per-lane slices of qX[b]: float4 indices sub + 8j.
    float4 qv[4];
    #pragma unroll
    for (int j = 0; j < 4; j++) qv[j] = qX4[(size_t)b * 32 + sub + 8 * j];

    // ||q||, reduced over the 8-lane group.
    float qs = 0.0f;
    #pragma unroll
    for (int j = 0; j < 4; j++)
        qs += qv[j].x * qv[j].x + qv[j].y * qv[j].y + qv[j].z * qv[j].z + qv[j].w * qv[j].w;
    #pragma unroll
    for (int off = 4; off; off >>= 1) qs += __shfl_xor_sync(0xFFFFFFFFu, qs, off);
    const float invqn = 1.0f / fmaxf(sqrtf(qs), 1e-8f);

    const float4* __restrict__ drow = dXs4   + (size_t)b * N * 32;
    const int*    __restrict__ lrow = labels + (size_t)b * N;

    // Lane k accumulates bin k. DELTA = 2/(NBIN-1) = 1/12.
    const float ck   = 1.0f - (float)lane * (2.0f / (float)(NBIN - 1));
    const float invD = (float)(NBIN - 1) * 0.5f;   // 12

    float accNum = 0.0f, accDen = 0.0f, accLab = 0.0f;

    const int nTiles = (N + 31) >> 5;      // 32-row tiles
    for (int t = gw; t < nTiles; t += nWarps) {
        const int tile = t << 5;
        const int cnt  = min(32, N - tile);
        const int lab32 = (lane < cnt) ? lrow[tile + lane] : 0;
        accLab += (float)lab32;

        #pragma unroll 2
        for (int i = 0; i < 8; i++) {      // 4 rows per iteration
            const int r0 = tile + (i << 2);
            if (r0 >= N) break;
            const int myrow   = r0 + grp;
            const int loadrow = (myrow < N) ? myrow : (N - 1);
            const float4* __restrict__ p = drow + (size_t)loadrow * 32 + sub;

            float d = 0.0f, sq = 0.0f;
            #pragma unroll
            for (int j = 0; j < 4; j++) {
                const float4 x = p[8 * j];
                d  += qv[j].x * x.x + qv[j].y * x.y + qv[j].z * x.z + qv[j].w * x.w;
                sq += x.x * x.x + x.y * x.y + x.z * x.z + x.w * x.w;
            }
            #pragma unroll
            for (int off = 4; off; off >>= 1) {
                d  += __shfl_xor_sync(0xFFFFFFFFu, d,  off);
                sq += __shfl_xor_sync(0xFFFFFFFFu, sq, off);
            }
            const float dn  = fmaxf(sqrtf(sq), 1e-8f);
            const float sim = __fdividef(d * invqn, dn);

            #pragma unroll
            for (int r = 0; r < 4; r++) {
                if (r0 + r >= N) break;   // uniform branch
                const float simr = __shfl_sync(0xFFFFFFFFu, sim, r << 3);
                const float labr = (float)__shfl_sync(0xFFFFFFFFu, lab32, (i << 2) + r);
                const float sa = fmaxf(0.0f, fmaf(-invD, fabsf(simr - ck), 1.0f));
                accDen += sa;
                accNum += sa * labr;
            }
        }
    }

    // Warp-reduce the per-lane label partials.
    #pragma unroll
    for (int off = 16; off; off >>= 1)
        accLab += __shfl_xor_sync(0xFFFFFFFFu, accLab, off);

    // Block-level combine in smem, then one plain store per bin.
    __shared__ float s_num[NBIN], s_den[NBIN], s_lab;
    if (threadIdx.x < NBIN) { s_num[threadIdx.x] = 0.0f; s_den[threadIdx.x] = 0.0f; }
    if (threadIdx.x == 0) s_lab = 0.0f;
    __syncthreads();
    if (lane < NBIN) {
        atomicAdd(&s_den[lane], accDen);
        atomicAdd(&s_num[lane], accNum);
    }
    if (lane == 0) atomicAdd(&s_lab, accLab);
    __syncthreads();

    const int slot = s * B + b;            // coalesced layout for the reducer
    if (threadIdx.x < NBIN) {
        g_pnum[slot * NBIN + threadIdx.x] = s_num[threadIdx.x];
        g_pden[slot * NBIN + threadIdx.x] = s_den[threadIdx.x];
    }
    if (threadIdx.x == 0) g_plab[slot] = s_lab;
}

// ---------------------------------------------------------------------------
// Reduce partials over slices, then cumsum -> precision/recall -> AP -> mean.
// ---------------------------------------------------------------------------
__global__ void qap_final(float* __restrict__ out, int B, int S) {
    __shared__ float sn[MAX_B * NBIN], sd[MAX_B * NBIN], sl[MAX_B];
    const int t     = threadIdx.x;
    const int total = B * NBIN;

    for (int i = t; i < total; i += blockDim.x) {
        float a = 0.0f, c = 0.0f;
        for (int sidx = 0; sidx < S; sidx++) {     // coalesced: stride = total
            a += g_pnum[sidx * total + i];
            c += g_pden[sidx * total + i];
        }
        sn[i] = a; sd[i] = c;
    }
    if (t < B) {
        float l = 0.0f;
        for (int sidx = 0; sidx < S; sidx++) l += g_plab[sidx * B + t];
        sl[t] = l;
    }
    __syncthreads();

    float ap = 0.0f;
    if (t < B) {
        float pd = 0.0f;           // cumsum num_per_bin  ("pDen")
        float pn = 1e-16f;         // EPS_P + cumsum den_per_bin ("pNum")
        const float invLab = 1.0f / sl[t];
        #pragma unroll
        for (int k = 0; k < NBIN; k++) {
            const float nm = sn[t * NBIN + k];
            const float dn = sd[t * NBIN + k];
            pd += nm;
            pn += dn;
            ap += (pd / pn) * (nm * invLab);
        }
    }
    if (t < 32) {
        #pragma unroll
        for (int off = 16; off; off >>= 1) ap += __shfl_xor_sync(0xFFFFFFFFu, ap, off);
        if (t == 0) out[0] = ap / (float)B;
    }
}

// ---------------------------------------------------------------------------
extern "C" void kernel_launch(void* const* d_in, const int* in_sizes, int n_in,
                              void* d_out, int out_size) {
    const float4* qX4    = (const float4*)d_in[0];
    const float4* dXs4   = (const float4*)d_in[1];
    const int*    labels = (const int*)d_in[2];
    float* out = (float*)d_out;

    const int M = 128;
    const int B = in_sizes[0] / M;               // 16
    const int N = in_sizes[1] / in_sizes[0];     // 50000

    // One exact wave: 148 SMs * 4 blocks/SM = 592 blocks.
    int S = (592 + B - 1) / B;                   // slices per batch (37 for B=16)
    if ((size_t)B * S > MAX_SLOTS) S = MAX_SLOTS / B;

    qap_main<<<B * S, WARPS_PER_BLOCK * 32>>>(qX4, dXs4, labels, B, N, S);
    qap_final<<<1, 512>>>(out, B, S);
}